// round 1
// baseline (speedup 1.0000x reference)
#include <cuda_runtime.h>
#include <cuda_bf16.h>
#include <cstdint>

// Inputs (metadata order):
//   0: positions  float32  (N_ML+N_MM)*3
//   1: cell       float32  9
//   2: cutoffs    float32  2
//   3: shifts     int32    S*3          (S=13)
//   4: ml_idx     int32    n_ml         (128)
//   5: mm_idx     int32    n_mm         (8192)
//
// Output (float32, flattened concat of reference return tuple):
//   [0,   2P)   idx_i
//   [2P,  4P)   idx_j
//   [4P, 10P)   offsets_cart (2P x 3 row-major)
//   [10P, 12P)  d2_full
//   [12P, 16P)  masks (2 x 2P)
// where P = (S+1)*n_ml*n_mm, bi-directional duplication:
//   idx_i = [pi_all, pj_all], idx_j = [pj_all, pi_all]
//   offsets = [-sv, +sv], d2_full = [d2, d2]

__global__ __launch_bounds__(256)
void nbrlist_kernel(const float* __restrict__ pos,
                    const float* __restrict__ cell,
                    const float* __restrict__ cutoffs,
                    const int*   __restrict__ shifts,
                    const int*   __restrict__ ml_idx,
                    const int*   __restrict__ mm_idx,
                    float* __restrict__ out,
                    int n_ml, int n_mm, int S_img, long long P)
{
    long long tid = (long long)blockIdx.x * blockDim.x + threadIdx.x;
    long long p = tid * 4;
    if (p >= P) return;

    const long long P0 = (long long)n_ml * n_mm;

    int s = (int)(p / P0);
    long long k = p - (long long)s * P0;
    int i  = (int)(k / n_mm);
    int j0 = (int)(k - (long long)i * n_mm);

    // cell + cutoffs (tiny, L1/const-cached)
    const float c00 = __ldg(cell + 0), c01 = __ldg(cell + 1), c02 = __ldg(cell + 2);
    const float c10 = __ldg(cell + 3), c11 = __ldg(cell + 4), c12 = __ldg(cell + 5);
    const float c20 = __ldg(cell + 6), c21 = __ldg(cell + 7), c22 = __ldg(cell + 8);
    const float cut0 = __ldg(cutoffs + 0), cut1 = __ldg(cutoffs + 1);
    const float c0sq = cut0 * cut0, c1sq = cut1 * cut1;

    const long long base_ii = 0;
    const long long base_ij = 2 * P;
    const long long base_of = 4 * P;
    const long long base_d2 = 10 * P;
    const long long base_mk = 12 * P;

    // fast path: whole 4-group shares (s, i), j0..j0+3 valid
    bool fast = (p + 3 < P) && ((k / n_mm) == ((k + 3) / n_mm));

    if (fast) {
        // shift vec for image s (s==0 -> zero shift)
        float sf0 = 0.f, sf1 = 0.f, sf2 = 0.f;
        if (s > 0) {
            sf0 = (float)__ldg(shifts + (s - 1) * 3 + 0);
            sf1 = (float)__ldg(shifts + (s - 1) * 3 + 1);
            sf2 = (float)__ldg(shifts + (s - 1) * 3 + 2);
        }
        const float svx = sf0 * c00 + sf1 * c10 + sf2 * c20;
        const float svy = sf0 * c01 + sf1 * c11 + sf2 * c21;
        const float svz = sf0 * c02 + sf1 * c12 + sf2 * c22;

        const int ia = __ldg(ml_idx + i);
        const float pix = __ldg(pos + 3 * ia + 0);
        const float piy = __ldg(pos + 3 * ia + 1);
        const float piz = __ldg(pos + 3 * ia + 2);

        float d2v[4], pjf[4];
        #pragma unroll
        for (int u = 0; u < 4; u++) {
            const int ja = __ldg(mm_idx + j0 + u);
            const float dx = pix - __ldg(pos + 3 * ja + 0) + svx;
            const float dy = piy - __ldg(pos + 3 * ja + 1) + svy;
            const float dz = piz - __ldg(pos + 3 * ja + 2) + svz;
            d2v[u] = dx * dx + dy * dy + dz * dz;
            pjf[u] = (float)ja;
        }
        const float fi = (float)ia;

        const float4 v_fi = make_float4(fi, fi, fi, fi);
        const float4 v_pj = make_float4(pjf[0], pjf[1], pjf[2], pjf[3]);
        const float4 v_d2 = make_float4(d2v[0], d2v[1], d2v[2], d2v[3]);

        // idx_i = [pi_all, pj_all]
        *reinterpret_cast<float4*>(out + base_ii + p)     = v_fi;
        *reinterpret_cast<float4*>(out + base_ii + P + p) = v_pj;
        // idx_j = [pj_all, pi_all]
        *reinterpret_cast<float4*>(out + base_ij + p)     = v_pj;
        *reinterpret_cast<float4*>(out + base_ij + P + p) = v_fi;

        // offsets: first half = -sv, second half = +sv (3 floats/row, 4 rows = 3 float4)
        const float4 na = make_float4(-svx, -svy, -svz, -svx);
        const float4 nb = make_float4(-svy, -svz, -svx, -svy);
        const float4 nc = make_float4(-svz, -svx, -svy, -svz);
        float4* oneg = reinterpret_cast<float4*>(out + base_of + 3 * p);
        oneg[0] = na; oneg[1] = nb; oneg[2] = nc;
        const float4 pa = make_float4(svx, svy, svz, svx);
        const float4 pb = make_float4(svy, svz, svx, svy);
        const float4 pc = make_float4(svz, svx, svy, svz);
        float4* opos = reinterpret_cast<float4*>(out + base_of + 3 * P + 3 * p);
        opos[0] = pa; opos[1] = pb; opos[2] = pc;

        // d2_full = [d2, d2]
        *reinterpret_cast<float4*>(out + base_d2 + p)     = v_d2;
        *reinterpret_cast<float4*>(out + base_d2 + P + p) = v_d2;

        // masks (2, 2P)
        const float4 m0 = make_float4(d2v[0] < c0sq ? 1.f : 0.f,
                                      d2v[1] < c0sq ? 1.f : 0.f,
                                      d2v[2] < c0sq ? 1.f : 0.f,
                                      d2v[3] < c0sq ? 1.f : 0.f);
        const float4 m1 = make_float4(d2v[0] < c1sq ? 1.f : 0.f,
                                      d2v[1] < c1sq ? 1.f : 0.f,
                                      d2v[2] < c1sq ? 1.f : 0.f,
                                      d2v[3] < c1sq ? 1.f : 0.f);
        *reinterpret_cast<float4*>(out + base_mk + p)         = m0;
        *reinterpret_cast<float4*>(out + base_mk + P + p)     = m0;
        *reinterpret_cast<float4*>(out + base_mk + 2 * P + p) = m1;
        *reinterpret_cast<float4*>(out + base_mk + 3 * P + p) = m1;
    } else {
        // generic scalar path (group crosses an (s,i) boundary or tail)
        for (int u = 0; u < 4; u++) {
            long long pp = p + u;
            if (pp >= P) break;
            int ss = (int)(pp / P0);
            long long kk = pp - (long long)ss * P0;
            int ii = (int)(kk / n_mm);
            int jj = (int)(kk - (long long)ii * n_mm);

            float sf0 = 0.f, sf1 = 0.f, sf2 = 0.f;
            if (ss > 0) {
                sf0 = (float)__ldg(shifts + (ss - 1) * 3 + 0);
                sf1 = (float)__ldg(shifts + (ss - 1) * 3 + 1);
                sf2 = (float)__ldg(shifts + (ss - 1) * 3 + 2);
            }
            const float svx = sf0 * c00 + sf1 * c10 + sf2 * c20;
            const float svy = sf0 * c01 + sf1 * c11 + sf2 * c21;
            const float svz = sf0 * c02 + sf1 * c12 + sf2 * c22;

            const int ia = __ldg(ml_idx + ii);
            const int ja = __ldg(mm_idx + jj);
            const float dx = __ldg(pos + 3 * ia + 0) - __ldg(pos + 3 * ja + 0) + svx;
            const float dy = __ldg(pos + 3 * ia + 1) - __ldg(pos + 3 * ja + 1) + svy;
            const float dz = __ldg(pos + 3 * ia + 2) - __ldg(pos + 3 * ja + 2) + svz;
            const float d2 = dx * dx + dy * dy + dz * dz;
            const float fi = (float)ia, fj = (float)ja;

            out[base_ii + pp]     = fi;
            out[base_ii + P + pp] = fj;
            out[base_ij + pp]     = fj;
            out[base_ij + P + pp] = fi;
            out[base_of + 3 * pp + 0] = -svx;
            out[base_of + 3 * pp + 1] = -svy;
            out[base_of + 3 * pp + 2] = -svz;
            out[base_of + 3 * P + 3 * pp + 0] = svx;
            out[base_of + 3 * P + 3 * pp + 1] = svy;
            out[base_of + 3 * P + 3 * pp + 2] = svz;
            out[base_d2 + pp]     = d2;
            out[base_d2 + P + pp] = d2;
            const float m0 = d2 < c0sq ? 1.f : 0.f;
            const float m1 = d2 < c1sq ? 1.f : 0.f;
            out[base_mk + pp]         = m0;
            out[base_mk + P + pp]     = m0;
            out[base_mk + 2 * P + pp] = m1;
            out[base_mk + 3 * P + pp] = m1;
        }
    }
}

extern "C" void kernel_launch(void* const* d_in, const int* in_sizes, int n_in,
                              void* d_out, int out_size)
{
    const float* pos     = (const float*)d_in[0];
    const float* cell    = (const float*)d_in[1];
    const float* cutoffs = (const float*)d_in[2];
    const int*   shifts  = (const int*)d_in[3];
    const int*   ml_idx  = (const int*)d_in[4];
    const int*   mm_idx  = (const int*)d_in[5];

    const int n_ml  = in_sizes[4];
    const int n_mm  = in_sizes[5];
    const int S     = in_sizes[3] / 3;
    const int S_img = S + 1;
    const long long P = (long long)S_img * n_ml * n_mm;

    const long long n_groups = (P + 3) / 4;
    const int threads = 256;
    const long long blocks = (n_groups + threads - 1) / threads;

    nbrlist_kernel<<<(unsigned)blocks, threads>>>(
        pos, cell, cutoffs, shifts, ml_idx, mm_idx,
        (float*)d_out, n_ml, n_mm, S_img, P);
}

// round 2
// speedup vs baseline: 1.0757x; 1.0757x over previous
#include <cuda_runtime.h>
#include <cuda_bf16.h>
#include <cstdint>

// Inputs (metadata order):
//   0: positions float32 (N_ML+N_MM)*3   1: cell float32 9   2: cutoffs float32 2
//   3: shifts int32 S*3 (S=13)           4: ml_idx int32     5: mm_idx int32
//
// Output (float32 flat): [0,2P) idx_i | [2P,4P) idx_j | [4P,10P) offsets(2P x 3)
//                        [10P,12P) d2_full | [12P,16P) masks(2 x 2P)
// P=(S+1)*n_ml*n_mm; bi-dir: idx_i=[pi,pj], idx_j=[pj,pi], offsets=[-sv,+sv], d2=[d2,d2]

__global__ __launch_bounds__(256)
void nbrlist_kernel(const float* __restrict__ pos,
                    const float* __restrict__ cell,
                    const float* __restrict__ cutoffs,
                    const int*   __restrict__ shifts,
                    const int*   __restrict__ ml_idx,
                    const int*   __restrict__ mm_idx,
                    float* __restrict__ out,
                    int n_ml, int n_mm, int S_img, long long P)
{
    long long tid = (long long)blockIdx.x * blockDim.x + threadIdx.x;
    long long p = tid * 4;
    if (p >= P) return;

    const long long P0 = (long long)n_ml * n_mm;

    int s = (int)(p / P0);
    long long k = p - (long long)s * P0;
    int i  = (int)(k / n_mm);
    int j0 = (int)(k - (long long)i * n_mm);

    const float c00 = __ldg(cell + 0), c01 = __ldg(cell + 1), c02 = __ldg(cell + 2);
    const float c10 = __ldg(cell + 3), c11 = __ldg(cell + 4), c12 = __ldg(cell + 5);
    const float c20 = __ldg(cell + 6), c21 = __ldg(cell + 7), c22 = __ldg(cell + 8);
    const float cut0 = __ldg(cutoffs + 0), cut1 = __ldg(cutoffs + 1);
    const float c0sq = cut0 * cut0, c1sq = cut1 * cut1;

    const long long base_ii = 0;
    const long long base_ij = 2 * P;
    const long long base_of = 4 * P;
    const long long base_d2 = 10 * P;
    const long long base_mk = 12 * P;

    bool fast = (p + 3 < P) && ((k / n_mm) == ((k + 3) / n_mm)) && ((j0 & 3) == 0);

    if (fast) {
        float sf0 = 0.f, sf1 = 0.f, sf2 = 0.f;
        if (s > 0) {
            sf0 = (float)__ldg(shifts + (s - 1) * 3 + 0);
            sf1 = (float)__ldg(shifts + (s - 1) * 3 + 1);
            sf2 = (float)__ldg(shifts + (s - 1) * 3 + 2);
        }
        const float svx = sf0 * c00 + sf1 * c10 + sf2 * c20;
        const float svy = sf0 * c01 + sf1 * c11 + sf2 * c21;
        const float svz = sf0 * c02 + sf1 * c12 + sf2 * c22;

        const int ia = __ldg(ml_idx + i);
        const float pix = __ldg(pos + 3 * ia + 0) + svx;
        const float piy = __ldg(pos + 3 * ia + 1) + svy;
        const float piz = __ldg(pos + 3 * ia + 2) + svz;

        // mm_idx group via one int4 load (j0 % 4 == 0 -> 16B aligned)
        const int4 jv = __ldg(reinterpret_cast<const int4*>(mm_idx + j0));

        float d2v[4], pjf[4];
        pjf[0] = (float)jv.x; pjf[1] = (float)jv.y;
        pjf[2] = (float)jv.z; pjf[3] = (float)jv.w;

        const bool contig = (jv.w == jv.x + 3) && (((3 * jv.x) & 3) == 0);
        if (contig) {
            // 4 consecutive positions = 48B = 3 x float4 (vectorized gather)
            const float4* pb = reinterpret_cast<const float4*>(pos + 3 * jv.x);
            const float4 v0 = __ldg(pb + 0);
            const float4 v1 = __ldg(pb + 1);
            const float4 v2 = __ldg(pb + 2);
            {
                const float dx = pix - v0.x, dy = piy - v0.y, dz = piz - v0.z;
                d2v[0] = dx * dx + dy * dy + dz * dz;
            }
            {
                const float dx = pix - v0.w, dy = piy - v1.x, dz = piz - v1.y;
                d2v[1] = dx * dx + dy * dy + dz * dz;
            }
            {
                const float dx = pix - v1.z, dy = piy - v1.w, dz = piz - v2.x;
                d2v[2] = dx * dx + dy * dy + dz * dz;
            }
            {
                const float dx = pix - v2.y, dy = piy - v2.z, dz = piz - v2.w;
                d2v[3] = dx * dx + dy * dy + dz * dz;
            }
        } else {
            const int jidx[4] = {jv.x, jv.y, jv.z, jv.w};
            #pragma unroll
            for (int u = 0; u < 4; u++) {
                const float dx = pix - __ldg(pos + 3 * jidx[u] + 0);
                const float dy = piy - __ldg(pos + 3 * jidx[u] + 1);
                const float dz = piz - __ldg(pos + 3 * jidx[u] + 2);
                d2v[u] = dx * dx + dy * dy + dz * dz;
            }
        }

        const float fi = (float)ia;
        const float4 v_fi = make_float4(fi, fi, fi, fi);
        const float4 v_pj = make_float4(pjf[0], pjf[1], pjf[2], pjf[3]);
        const float4 v_d2 = make_float4(d2v[0], d2v[1], d2v[2], d2v[3]);

        // idx_i = [pi, pj] ; idx_j = [pj, pi]   (streaming stores: write-once data)
        __stcs(reinterpret_cast<float4*>(out + base_ii + p),     v_fi);
        __stcs(reinterpret_cast<float4*>(out + base_ii + P + p), v_pj);
        __stcs(reinterpret_cast<float4*>(out + base_ij + p),     v_pj);
        __stcs(reinterpret_cast<float4*>(out + base_ij + P + p), v_fi);

        // offsets: [-sv, +sv], 3 floats/row, 4 rows -> 3 float4 each half
        float4* oneg = reinterpret_cast<float4*>(out + base_of + 3 * p);
        __stcs(oneg + 0, make_float4(-svx, -svy, -svz, -svx));
        __stcs(oneg + 1, make_float4(-svy, -svz, -svx, -svy));
        __stcs(oneg + 2, make_float4(-svz, -svx, -svy, -svz));
        float4* opos = reinterpret_cast<float4*>(out + base_of + 3 * P + 3 * p);
        __stcs(opos + 0, make_float4(svx, svy, svz, svx));
        __stcs(opos + 1, make_float4(svy, svz, svx, svy));
        __stcs(opos + 2, make_float4(svz, svx, svy, svz));

        __stcs(reinterpret_cast<float4*>(out + base_d2 + p),     v_d2);
        __stcs(reinterpret_cast<float4*>(out + base_d2 + P + p), v_d2);

        const float4 m0 = make_float4(d2v[0] < c0sq ? 1.f : 0.f,
                                      d2v[1] < c0sq ? 1.f : 0.f,
                                      d2v[2] < c0sq ? 1.f : 0.f,
                                      d2v[3] < c0sq ? 1.f : 0.f);
        const float4 m1 = make_float4(d2v[0] < c1sq ? 1.f : 0.f,
                                      d2v[1] < c1sq ? 1.f : 0.f,
                                      d2v[2] < c1sq ? 1.f : 0.f,
                                      d2v[3] < c1sq ? 1.f : 0.f);
        __stcs(reinterpret_cast<float4*>(out + base_mk + p),         m0);
        __stcs(reinterpret_cast<float4*>(out + base_mk + P + p),     m0);
        __stcs(reinterpret_cast<float4*>(out + base_mk + 2 * P + p), m1);
        __stcs(reinterpret_cast<float4*>(out + base_mk + 3 * P + p), m1);
    } else {
        for (int u = 0; u < 4; u++) {
            long long pp = p + u;
            if (pp >= P) break;
            int ss = (int)(pp / P0);
            long long kk = pp - (long long)ss * P0;
            int ii = (int)(kk / n_mm);
            int jj = (int)(kk - (long long)ii * n_mm);

            float sf0 = 0.f, sf1 = 0.f, sf2 = 0.f;
            if (ss > 0) {
                sf0 = (float)__ldg(shifts + (ss - 1) * 3 + 0);
                sf1 = (float)__ldg(shifts + (ss - 1) * 3 + 1);
                sf2 = (float)__ldg(shifts + (ss - 1) * 3 + 2);
            }
            const float svx = sf0 * c00 + sf1 * c10 + sf2 * c20;
            const float svy = sf0 * c01 + sf1 * c11 + sf2 * c21;
            const float svz = sf0 * c02 + sf1 * c12 + sf2 * c22;

            const int ia = __ldg(ml_idx + ii);
            const int ja = __ldg(mm_idx + jj);
            const float dx = __ldg(pos + 3 * ia + 0) - __ldg(pos + 3 * ja + 0) + svx;
            const float dy = __ldg(pos + 3 * ia + 1) - __ldg(pos + 3 * ja + 1) + svy;
            const float dz = __ldg(pos + 3 * ia + 2) - __ldg(pos + 3 * ja + 2) + svz;
            const float d2 = dx * dx + dy * dy + dz * dz;
            const float fi = (float)ia, fj = (float)ja;

            out[base_ii + pp]     = fi;
            out[base_ii + P + pp] = fj;
            out[base_ij + pp]     = fj;
            out[base_ij + P + pp] = fi;
            out[base_of + 3 * pp + 0] = -svx;
            out[base_of + 3 * pp + 1] = -svy;
            out[base_of + 3 * pp + 2] = -svz;
            out[base_of + 3 * P + 3 * pp + 0] = svx;
            out[base_of + 3 * P + 3 * pp + 1] = svy;
            out[base_of + 3 * P + 3 * pp + 2] = svz;
            out[base_d2 + pp]     = d2;
            out[base_d2 + P + pp] = d2;
            const float m0 = d2 < c0sq ? 1.f : 0.f;
            const float m1 = d2 < c1sq ? 1.f : 0.f;
            out[base_mk + pp]         = m0;
            out[base_mk + P + pp]     = m0;
            out[base_mk + 2 * P + pp] = m1;
            out[base_mk + 3 * P + pp] = m1;
        }
    }
}

extern "C" void kernel_launch(void* const* d_in, const int* in_sizes, int n_in,
                              void* d_out, int out_size)
{
    const float* pos     = (const float*)d_in[0];
    const float* cell    = (const float*)d_in[1];
    const float* cutoffs = (const float*)d_in[2];
    const int*   shifts  = (const int*)d_in[3];
    const int*   ml_idx  = (const int*)d_in[4];
    const int*   mm_idx  = (const int*)d_in[5];

    const int n_ml  = in_sizes[4];
    const int n_mm  = in_sizes[5];
    const int S     = in_sizes[3] / 3;
    const int S_img = S + 1;
    const long long P = (long long)S_img * n_ml * n_mm;

    const long long n_groups = (P + 3) / 4;
    const int threads = 256;
    const long long blocks = (n_groups + threads - 1) / threads;

    nbrlist_kernel<<<(unsigned)blocks, threads>>>(
        pos, cell, cutoffs, shifts, ml_idx, mm_idx,
        (float*)d_out, n_ml, n_mm, S_img, P);
}